// round 2
// baseline (speedup 1.0000x reference)
#include <cuda_runtime.h>
#include <cuda_fp16.h>

#define GRIDSZ 32
#define BATCH  16
#define NPTS   131072
#define GCELLS (GRIDSZ * GRIDSZ * GRIDSZ)   // 32768
#define TPB    512
#define REPL   9                            // CTAs per batch -> 144 CTAs total

// dynamic smem: half2 xy[GCELLS] (128KB) + half z[GCELLS] (64KB) = 192KB
#define SMEM_BYTES (GCELLS * sizeof(__half2) + GCELLS * sizeof(__half))

// ---------------------------------------------------------------------------
// Single fused kernel: per-CTA constant precompute + fp16 table build in smem
// + transform/gather/reduce. grid = (REPL, BATCH), 1 CTA per SM (192KB smem).
// ---------------------------------------------------------------------------
__global__ void __launch_bounds__(TPB, 1)
sym_loss_kernel(const float* __restrict__ points,
                const float* __restrict__ closest,
                const float* __restrict__ out6,
                float* __restrict__ d_out) {
    extern __shared__ char dyn_smem[];
    __half2* __restrict__ s_xy = (__half2*)dyn_smem;                       // 128KB
    __half*  __restrict__ s_z  = (__half*)(dyn_smem + GCELLS * sizeof(__half2)); // 64KB
    __shared__ float sc[72];
    __shared__ float wsum[TPB / 32];

    const int b   = blockIdx.y;
    const int r   = blockIdx.x;
    const int tid = threadIdx.x;

    // ---- per-(batch,transform) constants (threads 0..5, redundant per replica)
    if (tid < 6) {
        const float* q = out6 + (b * 6 + tid) * 4;
        float* c = sc + tid * 12;
        float q0 = q[0], q1 = q[1], q2 = q[2], q3 = q[3];
        if (tid < 3) {
            // reflection: t = n.p + d ; p' = p - t * (2n / |n|^2)
            float inv = 1.0f / (q0 * q0 + q1 * q1 + q2 * q2);
            c[0] = q0; c[1] = q1; c[2] = q2; c[3] = q3;
            c[4] = 2.0f * q0 * inv;
            c[5] = 2.0f * q1 * inv;
            c[6] = 2.0f * q2 * inv;
        } else {
            // rotation: fused 3x3 matrix (q p q^-1 with _qinv's single 1/||q||)
            float w = q0, x = q1, y = q2, z = q3;
            float vv = x * x + y * y + z * z;
            float s = rsqrtf(w * w + vv);
            float ww = w * w - vv;
            c[0] = s * (ww + 2.0f * x * x);
            c[1] = s * 2.0f * (x * y - w * z);
            c[2] = s * 2.0f * (x * z + w * y);
            c[3] = s * 2.0f * (x * y + w * z);
            c[4] = s * (ww + 2.0f * y * y);
            c[5] = s * 2.0f * (y * z - w * x);
            c[6] = s * 2.0f * (x * z - w * y);
            c[7] = s * 2.0f * (y * z + w * x);
            c[8] = s * (ww + 2.0f * z * z);
        }
    }

    // ---- build fp16 gather table in shared memory
    const float* __restrict__ cb = closest + (size_t)b * GCELLS * 3;
    for (int i = tid; i < GCELLS; i += TPB) {
        float x = cb[3 * i + 0];
        float y = cb[3 * i + 1];
        float z = cb[3 * i + 2];
        s_xy[i] = __floats2half2_rn(x, y);
        s_z[i]  = __float2half_rn(z);
    }
    __syncthreads();

    // ---- main loop over this replica's slice of points
    const float* __restrict__ pbase = points + (size_t)b * NPTS * 3;
    float acc = 0.0f;

    for (int n = r * TPB + tid; n < NPTS; n += REPL * TPB) {
        const float px = pbase[n * 3 + 0];
        const float py = pbase[n * 3 + 1];
        const float pz = pbase[n * 3 + 2];

        float sx[6], sy[6], sz[6];
#pragma unroll
        for (int j = 0; j < 3; j++) {          // reflections
            const float* c = sc + j * 12;
            float t = fmaf(c[0], px, fmaf(c[1], py, fmaf(c[2], pz, c[3])));
            sx[j] = fmaf(-t, c[4], px);
            sy[j] = fmaf(-t, c[5], py);
            sz[j] = fmaf(-t, c[6], pz);
        }
#pragma unroll
        for (int j = 0; j < 3; j++) {          // rotations
            const float* m = sc + (3 + j) * 12;
            sx[3 + j] = fmaf(m[0], px, fmaf(m[1], py, m[2] * pz));
            sy[3 + j] = fmaf(m[3], px, fmaf(m[4], py, m[5] * pz));
            sz[3 + j] = fmaf(m[6], px, fmaf(m[7], py, m[8] * pz));
        }

        // cell indices: clamp[0,32] -> trunc -> clip 31  ==  trunc(min(max(s,0), 31.99999809))
        int fl[6];
#pragma unroll
        for (int j = 0; j < 6; j++) {
            int ix = (int)fminf(fmaxf(sx[j], 0.0f), 31.99999809f);
            int iy = (int)fminf(fmaxf(sy[j], 0.0f), 31.99999809f);
            int iz = (int)fminf(fmaxf(sz[j], 0.0f), 31.99999809f);
            fl[j] = (ix << 10) + (iy << 5) + iz;
        }

        // batched smem gathers (12 independent LDS for MLP)
        __half2 cxy[6];
        __half  cz[6];
#pragma unroll
        for (int j = 0; j < 6; j++) { cxy[j] = s_xy[fl[j]]; cz[j] = s_z[fl[j]]; }

#pragma unroll
        for (int j = 0; j < 6; j++) {
            float2 f = __half22float2(cxy[j]);
            float fz = __half2float(cz[j]);
            float dx = sx[j] - f.x;
            float dy = sy[j] - f.y;
            float dz = sz[j] - fz;
            acc += sqrtf(fmaf(dx, dx, fmaf(dy, dy, dz * dz)));
        }
    }

    // ---- reduce
#pragma unroll
    for (int o = 16; o > 0; o >>= 1)
        acc += __shfl_down_sync(0xffffffffu, acc, o);
    if ((tid & 31) == 0) wsum[tid >> 5] = acc;
    __syncthreads();
    if (tid == 0) {
        float s = 0.0f;
#pragma unroll
        for (int w = 0; w < TPB / 32; w++) s += wsum[w];
        atomicAdd(d_out, s * (1.0f / BATCH));
    }
}

// ---------------------------------------------------------------------------
extern "C" void kernel_launch(void* const* d_in, const int* in_sizes, int n_in,
                              void* d_out, int out_size) {
    const float* output  = nullptr;
    const float* points  = nullptr;
    const float* closest = nullptr;
    for (int i = 0; i < n_in; i++) {
        if (in_sizes[i] == BATCH * 6 * 4)           output  = (const float*)d_in[i];
        else if (in_sizes[i] == BATCH * NPTS * 3)   points  = (const float*)d_in[i];
        else if (in_sizes[i] == BATCH * GCELLS * 3) closest = (const float*)d_in[i];
    }

    static bool attr_set = false;
    if (!attr_set) {
        cudaFuncSetAttribute(sym_loss_kernel,
                             cudaFuncAttributeMaxDynamicSharedMemorySize,
                             (int)SMEM_BYTES);
        attr_set = true;
    }

    cudaMemsetAsync(d_out, 0, sizeof(float));

    dim3 grid(REPL, BATCH);
    sym_loss_kernel<<<grid, TPB, SMEM_BYTES>>>(points, closest, output, (float*)d_out);
}

// round 3
// speedup vs baseline: 1.0340x; 1.0340x over previous
#include <cuda_runtime.h>

#define GRIDSZ 32
#define BATCH  16
#define NPTS   131072
#define GCELLS 32768
#define TPB    768
#define REPL   9                      // 9 x 16 = 144 CTAs, 1 per SM
#define NCHUNK (NPTS / 4)             // 32768 four-point chunks per batch
#define STAGE_CELLS  2048             // cells packed per build tile
#define STAGE_FLOATS (STAGE_CELLS * 3)

// dynamic smem: uint32 table[GCELLS] (128KB) + float stage[6144] (24KB)
#define SMEM_BYTES (GCELLS * 4 + STAGE_FLOATS * 4)

#define ENC_SCALE 31.96875f           // 1023/32 (exact)
#define DEC_SCALE (32.0f / 1023.0f)

__global__ void __launch_bounds__(TPB, 1)
sym_loss_kernel(const float* __restrict__ points,
                const float* __restrict__ closest,
                const float* __restrict__ out6,
                float* __restrict__ d_out) {
    extern __shared__ char dyn_smem[];
    unsigned int* __restrict__ s_tab = (unsigned int*)dyn_smem;          // 128KB
    float* __restrict__ s_stage = (float*)(dyn_smem + GCELLS * 4);       // 24KB
    __shared__ float sc[72];               // 6 affine transforms x (3x3 M + t)
    __shared__ float wsum[TPB / 32];

    const int b   = blockIdx.y;
    const int r   = blockIdx.x;
    const int tid = threadIdx.x;

    // ---- affine constants: s = M*p + t, layout sc[j*12 + {m00..m22, t0,t1,t2}]
    if (tid < 6) {
        const float* q = out6 + (b * 6 + tid) * 4;
        float* c = sc + tid * 12;
        float q0 = q[0], q1 = q[1], q2 = q[2], q3 = q[3];
        if (tid < 3) {
            // reflection: p' = p - (n.p + d) * a,  a = 2n/|n|^2
            float inv = 1.0f / (q0 * q0 + q1 * q1 + q2 * q2);
            float a0 = 2.0f * q0 * inv, a1 = 2.0f * q1 * inv, a2 = 2.0f * q2 * inv;
            c[0] = 1.0f - a0 * q0; c[1] =       -a0 * q1; c[2] =       -a0 * q2;
            c[3] =       -a1 * q0; c[4] = 1.0f - a1 * q1; c[5] =       -a1 * q2;
            c[6] =       -a2 * q0; c[7] =       -a2 * q1; c[8] = 1.0f - a2 * q2;
            c[9] = -q3 * a0; c[10] = -q3 * a1; c[11] = -q3 * a2;
        } else {
            // rotation: (q p q~) / ||q||  (reference's _qinv uses one 1/||q||)
            float w = q0, x = q1, y = q2, z = q3;
            float vv = x * x + y * y + z * z;
            float s = rsqrtf(w * w + vv);
            float ww = w * w - vv;
            c[0] = s * (ww + 2.0f * x * x);
            c[1] = s * 2.0f * (x * y - w * z);
            c[2] = s * 2.0f * (x * z + w * y);
            c[3] = s * 2.0f * (x * y + w * z);
            c[4] = s * (ww + 2.0f * y * y);
            c[5] = s * 2.0f * (y * z - w * x);
            c[6] = s * 2.0f * (x * z - w * y);
            c[7] = s * 2.0f * (y * z + w * x);
            c[8] = s * (ww + 2.0f * z * z);
            c[9] = 0.0f; c[10] = 0.0f; c[11] = 0.0f;
        }
    }

    // ---- build packed 10:10:10 table via coalesced float4 staging
    const float4* __restrict__ cb4 =
        (const float4*)(closest + (size_t)b * GCELLS * 3);
    for (int T = 0; T < GCELLS / STAGE_CELLS; T++) {     // 16 tiles
#pragma unroll
        for (int k = 0; k < 2; k++) {                    // 1536 float4 / 768 thr
            int i = tid + k * TPB;
            ((float4*)s_stage)[i] = cb4[T * (STAGE_FLOATS / 4) + i];
        }
        __syncthreads();
#pragma unroll
        for (int k = 0; k < 3; k++) {                    // 2048 cells
            int m = tid + k * TPB;
            if (m < STAGE_CELLS) {
                float x = s_stage[3 * m + 0];
                float y = s_stage[3 * m + 1];
                float z = s_stage[3 * m + 2];
                unsigned qx = min(1023, (int)fmaf(x, ENC_SCALE, 0.5f));
                unsigned qy = min(1023, (int)fmaf(y, ENC_SCALE, 0.5f));
                unsigned qz = min(1023, (int)fmaf(z, ENC_SCALE, 0.5f));
                s_tab[T * STAGE_CELLS + m] = (qx << 20) | (qy << 10) | qz;
            }
        }
        __syncthreads();
    }

    // ---- main loop: 4 points per chunk, 6 affine transforms each
    const float4* __restrict__ pb4 =
        (const float4*)(points + (size_t)b * NPTS * 3);
    float acc = 0.0f;

    for (int c = r * TPB + tid; c < NCHUNK; c += REPL * TPB) {
        float4 f0 = pb4[3 * c + 0];
        float4 f1 = pb4[3 * c + 1];
        float4 f2 = pb4[3 * c + 2];
        float PX[4] = {f0.x, f0.w, f1.z, f2.y};
        float PY[4] = {f0.y, f1.x, f1.w, f2.z};
        float PZ[4] = {f0.z, f1.y, f2.x, f2.w};

#pragma unroll
        for (int j = 0; j < 6; j++) {
            const float* m = sc + j * 12;
            float m0 = m[0], m1 = m[1], m2 = m[2];
            float m3 = m[3], m4 = m[4], m5 = m[5];
            float m6 = m[6], m7 = m[7], m8 = m[8];
            float t0 = m[9], t1 = m[10], t2 = m[11];

            float sx[4], sy[4], sz[4];
            int fl[4];
#pragma unroll
            for (int p = 0; p < 4; p++) {
                sx[p] = fmaf(m0, PX[p], fmaf(m1, PY[p], fmaf(m2, PZ[p], t0)));
                sy[p] = fmaf(m3, PX[p], fmaf(m4, PY[p], fmaf(m5, PZ[p], t1)));
                sz[p] = fmaf(m6, PX[p], fmaf(m7, PY[p], fmaf(m8, PZ[p], t2)));
                int ix = (int)fminf(fmaxf(sx[p], 0.0f), 31.99999809f);
                int iy = (int)fminf(fmaxf(sy[p], 0.0f), 31.99999809f);
                int iz = (int)fminf(fmaxf(sz[p], 0.0f), 31.99999809f);
                fl[p] = (ix << 10) + (iy << 5) + iz;
            }

            unsigned u[4];
#pragma unroll
            for (int p = 0; p < 4; p++) u[p] = s_tab[fl[p]];

#pragma unroll
            for (int p = 0; p < 4; p++) {
                float cx = (float)(u[p] >> 20);
                float cy = (float)((u[p] >> 10) & 1023u);
                float cz = (float)(u[p] & 1023u);
                float dx = fmaf(cx, DEC_SCALE, -sx[p]);
                float dy = fmaf(cy, DEC_SCALE, -sy[p]);
                float dz = fmaf(cz, DEC_SCALE, -sz[p]);
                float d2 = fmaf(dx, dx, fmaf(dy, dy, dz * dz));
                acc += (d2 > 0.0f) ? d2 * rsqrtf(d2) : 0.0f;
            }
        }
    }

    // ---- reduce
#pragma unroll
    for (int o = 16; o > 0; o >>= 1)
        acc += __shfl_down_sync(0xffffffffu, acc, o);
    if ((tid & 31) == 0) wsum[tid >> 5] = acc;
    __syncthreads();
    if (tid == 0) {
        float s = 0.0f;
#pragma unroll
        for (int w = 0; w < TPB / 32; w++) s += wsum[w];
        atomicAdd(d_out, s * (1.0f / BATCH));
    }
}

// ---------------------------------------------------------------------------
extern "C" void kernel_launch(void* const* d_in, const int* in_sizes, int n_in,
                              void* d_out, int out_size) {
    const float* output  = nullptr;
    const float* points  = nullptr;
    const float* closest = nullptr;
    for (int i = 0; i < n_in; i++) {
        if (in_sizes[i] == BATCH * 6 * 4)           output  = (const float*)d_in[i];
        else if (in_sizes[i] == BATCH * NPTS * 3)   points  = (const float*)d_in[i];
        else if (in_sizes[i] == BATCH * GCELLS * 3) closest = (const float*)d_in[i];
    }

    cudaFuncSetAttribute(sym_loss_kernel,
                         cudaFuncAttributeMaxDynamicSharedMemorySize,
                         (int)SMEM_BYTES);

    cudaMemsetAsync(d_out, 0, sizeof(float));

    dim3 grid(REPL, BATCH);
    sym_loss_kernel<<<grid, TPB, SMEM_BYTES>>>(points, closest, output,
                                               (float*)d_out);
}